// round 8
// baseline (speedup 1.0000x reference)
#include <cuda_runtime.h>
#include <cuda_bf16.h>
#include <cstdint>

// Problem constants
#define NTOK 8192
#define DDIM 1024
#define HDIM 4096
#define NEXP 8
#define TOPK 2
#define CAP  2048          // (TOPK*NTOK)/NEXP
#define SLOTS (TOPK*NTOK)  // 16384

// ---------------- scratch (__device__ globals: allocation-free) ----------------
__device__ float g_scores[NTOK * NEXP];
__device__ float g_topv[NTOK * TOPK];
__device__ int   g_topi[NTOK * TOPK];
__device__ int   g_pos[SLOTS];
__device__ int   g_s2t[NEXP * CAP];
__device__ int   g_ce[NEXP];
// pre-split bf16 operands; uint4 backing guarantees 16B alignment
__device__ uint4 g_xh_[(size_t)NTOK * DDIM / 8];
__device__ uint4 g_xl_[(size_t)NTOK * DDIM / 8];
__device__ uint4 g_w1h_[(size_t)NEXP * HDIM * DDIM / 8];  // [E][n=H][k=D]
__device__ uint4 g_w1l_[(size_t)NEXP * HDIM * DDIM / 8];
__device__ uint4 g_w2h_[(size_t)NEXP * DDIM * HDIM / 8];  // [E][n=D][k=H]
__device__ uint4 g_w2l_[(size_t)NEXP * DDIM * HDIM / 8];
__device__ uint4 g_hh_[(size_t)NEXP * CAP * HDIM / 8];    // [slot][H]
__device__ uint4 g_hl_[(size_t)NEXP * CAP * HDIM / 8];
__device__ float g_y[(size_t)NEXP * CAP * DDIM];

#define BF16P(a) (( __nv_bfloat16*)(a))
#define CBF16P(a) ((const __nv_bfloat16*)(a))

// ---------------- init ----------------
__global__ void init_kernel() {
    int i = blockIdx.x * blockDim.x + threadIdx.x;
    if (i < NEXP * CAP) g_s2t[i] = -1;
    if (i < NEXP)       g_ce[i]  = 0;
}

// ---------------- split x ----------------
__global__ void split_x_kernel(const float* __restrict__ x) {
    int i = blockIdx.x * blockDim.x + threadIdx.x;
    const int NP = NTOK * DDIM / 2;
    if (i >= NP) return;
    float2 v = ((const float2*)x)[i];
    __nv_bfloat162 h = __floats2bfloat162_rn(v.x, v.y);
    float rx = v.x - __bfloat162float(h.x);
    float ry = v.y - __bfloat162float(h.y);
    __nv_bfloat162 l = __floats2bfloat162_rn(rx, ry);
    ((__nv_bfloat162*)g_xh_)[i] = h;
    ((__nv_bfloat162*)g_xl_)[i] = l;
}

// ---------------- transpose + split weights (device-referenced dests) ----------------
template<bool IS_W1>
__global__ void tsplit_kernel(const float* __restrict__ in, int K, int N) {
    __nv_bfloat16* oh = BF16P(IS_W1 ? g_w1h_ : g_w2h_);
    __nv_bfloat16* ol = BF16P(IS_W1 ? g_w1l_ : g_w2l_);
    __shared__ float t[32][33];
    int e = blockIdx.z;
    int n0 = blockIdx.x * 32, k0 = blockIdx.y * 32;
    const float* ine = in + (size_t)e * K * N;
    int tx = threadIdx.x, ty = threadIdx.y;
#pragma unroll
    for (int j = 0; j < 32; j += 8)
        t[ty + j][tx] = ine[(size_t)(k0 + ty + j) * N + n0 + tx];
    __syncthreads();
    size_t ob = (size_t)e * N * K;
#pragma unroll
    for (int j = 0; j < 32; j += 8) {
        float v = t[tx][ty + j];
        __nv_bfloat16 h = __float2bfloat16(v);
        __nv_bfloat16 l = __float2bfloat16(v - __bfloat162float(h));
        size_t o = ob + (size_t)(n0 + ty + j) * K + k0 + tx;
        oh[o] = h; ol[o] = l;
    }
}

// ---------------- gate ----------------
__global__ void gate_kernel(const float* __restrict__ x, const float* __restrict__ wg) {
    int gwarp = (blockIdx.x * blockDim.x + threadIdx.x) >> 5;
    int lane  = threadIdx.x & 31;
    if (gwarp >= NTOK) return;
    const float* xr = x + (size_t)gwarp * DDIM;
    float acc[NEXP];
#pragma unroll
    for (int e = 0; e < NEXP; e++) acc[e] = 0.f;
#pragma unroll 4
    for (int i = 0; i < DDIM / 32; i++) {
        int d = lane + 32 * i;
        float xv = xr[d];
        const float* wr = wg + d * NEXP;
#pragma unroll
        for (int e = 0; e < NEXP; e++) acc[e] = fmaf(xv, wr[e], acc[e]);
    }
#pragma unroll
    for (int off = 16; off > 0; off >>= 1)
#pragma unroll
        for (int e = 0; e < NEXP; e++)
            acc[e] += __shfl_xor_sync(0xffffffffu, acc[e], off);

    if (lane == 0) {
        float m = acc[0];
#pragma unroll
        for (int e = 1; e < NEXP; e++) m = fmaxf(m, acc[e]);
        float p[NEXP]; float s = 0.f;
#pragma unroll
        for (int e = 0; e < NEXP; e++) { p[e] = expf(acc[e] - m); s += p[e]; }
        float inv = 1.f / s;
#pragma unroll
        for (int e = 0; e < NEXP; e++) { p[e] *= inv; g_scores[gwarp * NEXP + e] = p[e]; }
        int i1 = 0; float v1 = p[0];
#pragma unroll
        for (int e = 1; e < NEXP; e++) if (p[e] > v1) { v1 = p[e]; i1 = e; }
        int i2 = -1; float v2 = -1.f;
#pragma unroll
        for (int e = 0; e < NEXP; e++) if (e != i1 && p[e] > v2) { v2 = p[e]; i2 = e; }
        g_topv[gwarp * 2 + 0] = v1; g_topv[gwarp * 2 + 1] = v2;
        g_topi[gwarp * 2 + 0] = i1; g_topi[gwarp * 2 + 1] = i2;
        atomicAdd(&g_ce[i1], 1);
    }
}

// ---------------- routing ----------------
__global__ void route_kernel() {
    const int T = 512, PER = SLOTS / T;
    int t = threadIdx.x;
    int lane = t & 31, w = t >> 5;
    int base = t * PER;

    int cnt[NEXP];
#pragma unroll
    for (int e = 0; e < NEXP; e++) cnt[e] = 0;
    int myexp[PER];
#pragma unroll
    for (int i = 0; i < PER; i++) {
        int s = base + i;
        int slot = s >> 13;
        int n = s & (NTOK - 1);
        int e = g_topi[n * 2 + slot];
        myexp[i] = e;
        cnt[e]++;
    }
    int inc[NEXP];
#pragma unroll
    for (int e = 0; e < NEXP; e++) inc[e] = cnt[e];
#pragma unroll
    for (int o = 1; o < 32; o <<= 1) {
#pragma unroll
        for (int e = 0; e < NEXP; e++) {
            int v = __shfl_up_sync(0xffffffffu, inc[e], o);
            if (lane >= o) inc[e] += v;
        }
    }
    __shared__ int wtot[16][NEXP], wexcl[16][NEXP];
    if (lane == 31)
#pragma unroll
        for (int e = 0; e < NEXP; e++) wtot[w][e] = inc[e];
    __syncthreads();
    if (t == 0) {
        int run[NEXP];
#pragma unroll
        for (int e = 0; e < NEXP; e++) run[e] = 0;
        for (int ww = 0; ww < 16; ww++)
#pragma unroll
            for (int e = 0; e < NEXP; e++) { wexcl[ww][e] = run[e]; run[e] += wtot[ww][e]; }
    }
    __syncthreads();
    int off[NEXP];
#pragma unroll
    for (int e = 0; e < NEXP; e++) off[e] = wexcl[w][e] + inc[e] - cnt[e];
#pragma unroll
    for (int i = 0; i < PER; i++) {
        int e = myexp[i];
        int p = off[e]++;
        int s = base + i;
        g_pos[s] = p;
        if (p < CAP) {
            int n = s & (NTOK - 1);
            g_s2t[e * CAP + p] = n;
        }
    }
}

// ---------------- bf16x3 GEMM: 128x64 tile, warp 32x32, 3 CTAs/SM target ----------------
#define BM 128
#define BN 64
#define BK 16
#define RPW 12   // uint32 words per row: 8 data (16 bf16) + 4 pad -> conflict-free

struct __align__(16) SmemT {
    uint32_t AH[2][BM][RPW];
    uint32_t AL[2][BM][RPW];
    uint32_t BH[2][BN][RPW];
    uint32_t BL[2][BN][RPW];
};  // 36864 bytes

__device__ __forceinline__ void cp16(uint32_t dst, const void* src, int bytes) {
    asm volatile("cp.async.cg.shared.global [%0], [%1], 16, %2;\n"
                 :: "r"(dst), "l"(src), "r"(bytes));
}
__device__ __forceinline__ void cp_commit() { asm volatile("cp.async.commit_group;\n" ::); }
__device__ __forceinline__ void cp_wait1()  { asm volatile("cp.async.wait_group 1;\n" ::); }
__device__ __forceinline__ void cp_wait0()  { asm volatile("cp.async.wait_group 0;\n" ::); }

__device__ __forceinline__ void mma_bf16(float* d, const uint32_t* a, const uint32_t* b) {
    asm volatile(
        "mma.sync.aligned.m16n8k16.row.col.f32.bf16.bf16.f32 "
        "{%0,%1,%2,%3}, {%4,%5,%6,%7}, {%8,%9}, {%0,%1,%2,%3};\n"
        : "+f"(d[0]), "+f"(d[1]), "+f"(d[2]), "+f"(d[3])
        : "r"(a[0]), "r"(a[1]), "r"(a[2]), "r"(a[3]), "r"(b[0]), "r"(b[1]));
}

// PHASE1: A = gather(xh/xl), B = w1 [E][H][D]; out g_hh/g_hl (relu+bias+split)
// PHASE2: A = g_hh/g_hl,     B = w2 [E][D][H]; out g_y (+bias)
template<int KD, int ND, bool PHASE1>
__global__ void __launch_bounds__(256, 3) gemm_kernel(const float* __restrict__ bias)
{
    __shared__ SmemT S;
    const int e  = blockIdx.z;
    const int m0 = blockIdx.y * BM;
    const int n0 = blockIdx.x * BN;
    const float* be = bias + (size_t)e * ND;
    const int tid = threadIdx.x;

    // ---- A loader: 256 chunks (128 rows x 2) ----
    const int arow = tid >> 1;
    const int akc  = (tid & 1) * 8;
    const int akw  = (tid & 1) * 4;
    const __nv_bfloat16 *asrcH, *asrcL;
    int abytes;
    if (PHASE1) {
        int tok = g_s2t[e * CAP + m0 + arow];
        abytes = (tok >= 0) ? 16 : 0;
        size_t ao = (tok >= 0) ? ((size_t)tok * KD + akc) : 0;
        asrcH = CBF16P(g_xh_) + ao;
        asrcL = CBF16P(g_xl_) + ao;
    } else {
        abytes = 16;
        size_t ao = (size_t)(e * CAP + m0 + arow) * KD + akc;
        asrcH = CBF16P(g_hh_) + ao;
        asrcL = CBF16P(g_hl_) + ao;
    }
    // ---- B loader: 128 chunks (64 rows x 2), threads 0..127 ----
    const int brow = (tid & 127) >> 1;
    const int bkc  = (tid & 1) * 8;
    const int bkw  = (tid & 1) * 4;
    const __nv_bfloat16 *bsrcH, *bsrcL;
    {
        size_t bo = (size_t)e * ND * KD + (size_t)(n0 + brow) * KD + bkc;
        bsrcH = CBF16P(PHASE1 ? g_w1h_ : g_w2h_) + bo;
        bsrcL = CBF16P(PHASE1 ? g_w1l_ : g_w2l_) + bo;
    }
    const bool bload = (tid < 128);

    auto load_stage = [&](int buf, int kt) {
        size_t ko = (size_t)kt * BK;
        cp16((uint32_t)__cvta_generic_to_shared(&S.AH[buf][arow][akw]), asrcH + ko, abytes);
        cp16((uint32_t)__cvta_generic_to_shared(&S.AL[buf][arow][akw]), asrcL + ko, abytes);
        if (bload) {
            cp16((uint32_t)__cvta_generic_to_shared(&S.BH[buf][brow][bkw]), bsrcH + ko, 16);
            cp16((uint32_t)__cvta_generic_to_shared(&S.BL[buf][brow][bkw]), bsrcL + ko, 16);
        }
        cp_commit();
    };

    // ---- warp tiling: 4x2 warps, each 32x32 ----
    const int warp = tid >> 5, lane = tid & 31;
    const int wm = warp >> 1, wn = warp & 1;
    const int mb = wm * 32, nb = wn * 32;
    const int lr = lane >> 2, lc = lane & 3;

    float acc[2][4][4];
#pragma unroll
    for (int mi = 0; mi < 2; mi++)
#pragma unroll
        for (int ni = 0; ni < 4; ni++)
#pragma unroll
            for (int r = 0; r < 4; r++) acc[mi][ni][r] = 0.f;

    const int KT = KD / BK;
    load_stage(0, 0);

    for (int kt = 0; kt < KT; kt++) {
        int buf = kt & 1;
        if (kt + 1 < KT) { load_stage(buf ^ 1, kt + 1); cp_wait1(); }
        else             { cp_wait0(); }
        __syncthreads();

        uint32_t afh[2][4], afl[2][4];
#pragma unroll
        for (int mi = 0; mi < 2; mi++) {
            int row = mb + mi * 16 + lr;
            afh[mi][0] = S.AH[buf][row][lc];
            afh[mi][1] = S.AH[buf][row + 8][lc];
            afh[mi][2] = S.AH[buf][row][lc + 4];
            afh[mi][3] = S.AH[buf][row + 8][lc + 4];
            afl[mi][0] = S.AL[buf][row][lc];
            afl[mi][1] = S.AL[buf][row + 8][lc];
            afl[mi][2] = S.AL[buf][row][lc + 4];
            afl[mi][3] = S.AL[buf][row + 8][lc + 4];
        }
        uint32_t bh[4][2], bl[4][2];
#pragma unroll
        for (int ni = 0; ni < 4; ni++) {
            int col = nb + ni * 8 + lr;
            bh[ni][0] = S.BH[buf][col][lc];
            bh[ni][1] = S.BH[buf][col][lc + 4];
            bl[ni][0] = S.BL[buf][col][lc];
            bl[ni][1] = S.BL[buf][col][lc + 4];
        }
        // three passes -> same-acc MMAs spaced 8 apart (break dep chains)
#pragma unroll
        for (int mi = 0; mi < 2; mi++)
#pragma unroll
            for (int ni = 0; ni < 4; ni++)
                mma_bf16(acc[mi][ni], afh[mi], bl[ni]);   // hi*lo
#pragma unroll
        for (int mi = 0; mi < 2; mi++)
#pragma unroll
            for (int ni = 0; ni < 4; ni++)
                mma_bf16(acc[mi][ni], afl[mi], bh[ni]);   // lo*hi
#pragma unroll
        for (int mi = 0; mi < 2; mi++)
#pragma unroll
            for (int ni = 0; ni < 4; ni++)
                mma_bf16(acc[mi][ni], afh[mi], bh[ni]);   // hi*hi
        __syncthreads();
    }

    // ---- epilogue ----
#pragma unroll
    for (int mi = 0; mi < 2; mi++) {
        int r = m0 + mb + mi * 16 + lr;
#pragma unroll
        for (int ni = 0; ni < 4; ni++) {
            int cb = n0 + nb + ni * 8 + 2 * lc;
            float b0 = be[cb], b1 = be[cb + 1];
            float v0 = acc[mi][ni][0] + b0, v1 = acc[mi][ni][1] + b1;
            float v2 = acc[mi][ni][2] + b0, v3 = acc[mi][ni][3] + b1;
            if (PHASE1) {
                v0 = fmaxf(v0, 0.f); v1 = fmaxf(v1, 0.f);
                v2 = fmaxf(v2, 0.f); v3 = fmaxf(v3, 0.f);
                size_t s0 = (size_t)(e * CAP + r) * HDIM + cb;
                size_t s1 = (size_t)(e * CAP + r + 8) * HDIM + cb;
                __nv_bfloat162 h0 = __floats2bfloat162_rn(v0, v1);
                __nv_bfloat162 h1 = __floats2bfloat162_rn(v2, v3);
                __nv_bfloat162 l0 = __floats2bfloat162_rn(v0 - __bfloat162float(h0.x),
                                                          v1 - __bfloat162float(h0.y));
                __nv_bfloat162 l1 = __floats2bfloat162_rn(v2 - __bfloat162float(h1.x),
                                                          v3 - __bfloat162float(h1.y));
                *(__nv_bfloat162*)(BF16P(g_hh_) + s0) = h0;
                *(__nv_bfloat162*)(BF16P(g_hh_) + s1) = h1;
                *(__nv_bfloat162*)(BF16P(g_hl_) + s0) = l0;
                *(__nv_bfloat162*)(BF16P(g_hl_) + s1) = l1;
            } else {
                float* Ce = g_y + (size_t)e * CAP * DDIM;
                *(float2*)&Ce[(size_t)r * DDIM + cb]       = make_float2(v0, v1);
                *(float2*)&Ce[(size_t)(r + 8) * DDIM + cb] = make_float2(v2, v3);
            }
        }
    }
}

// ---------------- combine ----------------
__global__ void combine_kernel(float* __restrict__ out) {
    int n = blockIdx.x, tid = threadIdx.x;
    float4 acc = make_float4(0.f, 0.f, 0.f, 0.f);
#pragma unroll
    for (int slot = 0; slot < TOPK; slot++) {
        int p = g_pos[slot * NTOK + n];
        if (p < CAP) {
            float v = g_topv[n * 2 + slot];
            int e = g_topi[n * 2 + slot];
            const float4* row = (const float4*)(g_y + (size_t)(e * CAP + p) * DDIM);
            float4 f = row[tid];
            acc.x += v * f.x; acc.y += v * f.y; acc.z += v * f.z; acc.w += v * f.w;
        }
    }
    ((float4*)(out + (size_t)n * DDIM))[tid] = acc;
}

// ---------------- aux loss ----------------
__global__ void aux_kernel(float* __restrict__ out, int out_size) {
    __shared__ float s[256];
    int tid = threadIdx.x;
    float p[NEXP];
#pragma unroll
    for (int e = 0; e < NEXP; e++) p[e] = 0.f;
    for (int i = tid; i < NTOK; i += 256)
#pragma unroll
        for (int e = 0; e < NEXP; e++) p[e] += g_scores[i * NEXP + e];

    float total = 0.f;
#pragma unroll
    for (int e = 0; e < NEXP; e++) {
        s[tid] = p[e];
        __syncthreads();
        for (int st = 128; st > 0; st >>= 1) {
            if (tid < st) s[tid] += s[tid + st];
            __syncthreads();
        }
        if (tid == 0) {
            float me = s[0] / (float)NTOK;
            float ce = (float)g_ce[e] / (float)NTOK;
            total += me * ce;
        }
        __syncthreads();
    }
    if (tid == 0) {
        float laux = (float)NEXP * total;
        for (long i = (long)NTOK * DDIM; i < (long)out_size; i++) out[i] = laux;
    }
}

// ---------------- launch ----------------
extern "C" void kernel_launch(void* const* d_in, const int* in_sizes, int n_in,
                              void* d_out, int out_size) {
    const float* x    = (const float*)d_in[0];
    const float* wg   = (const float*)d_in[1];
    const float* fc1w = (const float*)d_in[2];
    const float* fc1b = (const float*)d_in[3];
    const float* fc2w = (const float*)d_in[4];
    const float* fc2b = (const float*)d_in[5];
    float* out = (float*)d_out;
    (void)in_sizes; (void)n_in;

    init_kernel<<<(NEXP * CAP + 255) / 256, 256>>>();
    split_x_kernel<<<(NTOK * DDIM / 2 + 255) / 256, 256>>>(x);
    tsplit_kernel<true ><<<dim3(HDIM / 32, DDIM / 32, NEXP), dim3(32, 8)>>>(fc1w, DDIM, HDIM);
    tsplit_kernel<false><<<dim3(DDIM / 32, HDIM / 32, NEXP), dim3(32, 8)>>>(fc2w, HDIM, DDIM);
    gate_kernel<<<NTOK / 8, 256>>>(x, wg);
    route_kernel<<<1, 512>>>();
    gemm_kernel<DDIM, HDIM, true ><<<dim3(HDIM / BN, CAP / BM, NEXP), 256>>>(fc1b);
    gemm_kernel<HDIM, DDIM, false><<<dim3(DDIM / BN, CAP / BM, NEXP), 256>>>(fc2b);
    combine_kernel<<<NTOK, 256>>>(out);
    aux_kernel<<<1, 256>>>(out, out_size);
}

// round 9
// speedup vs baseline: 1.5138x; 1.5138x over previous
#include <cuda_runtime.h>
#include <cuda_bf16.h>
#include <cuda_fp16.h>
#include <cstdint>

// Problem constants
#define NTOK 8192
#define DDIM 1024
#define HDIM 4096
#define NEXP 8
#define TOPK 2
#define CAP  2048          // (TOPK*NTOK)/NEXP
#define SLOTS (TOPK*NTOK)  // 16384

// ---------------- scratch (__device__ globals: allocation-free) ----------------
__device__ float g_scores[NTOK * NEXP];
__device__ float g_topv[NTOK * TOPK];
__device__ int   g_topi[NTOK * TOPK];
__device__ int   g_pos[SLOTS];
__device__ int   g_s2t[NEXP * CAP];
__device__ int   g_ce[NEXP];
// fp16 operands; uint4 backing guarantees 16B alignment
__device__ uint4 g_xh_[(size_t)NTOK * DDIM / 8];          // x hi
__device__ uint4 g_xl_[(size_t)NTOK * DDIM / 8];          // x lo (exact residual)
__device__ uint4 g_w1h_[(size_t)NEXP * HDIM * DDIM / 8];  // [E][n=H][k=D] fp16(w1)
__device__ uint4 g_w2h_[(size_t)NEXP * DDIM * HDIM / 8];  // [E][n=D][k=H] fp16(w2)
__device__ uint4 g_hh_[(size_t)NEXP * CAP * HDIM / 8];    // h hi
__device__ uint4 g_hl_[(size_t)NEXP * CAP * HDIM / 8];    // h lo
__device__ float g_y[(size_t)NEXP * CAP * DDIM];

#define H16P(a) (( __half*)(a))
#define CH16P(a) ((const __half*)(a))

// ---------------- init ----------------
__global__ void init_kernel() {
    int i = blockIdx.x * blockDim.x + threadIdx.x;
    if (i < NEXP * CAP) g_s2t[i] = -1;
    if (i < NEXP)       g_ce[i]  = 0;
}

// ---------------- split x -> fp16 hi/lo ----------------
__global__ void split_x_kernel(const float* __restrict__ x) {
    int i = blockIdx.x * blockDim.x + threadIdx.x;
    const int NP = NTOK * DDIM / 2;
    if (i >= NP) return;
    float2 v = ((const float2*)x)[i];
    __half2 h = __floats2half2_rn(v.x, v.y);
    float rx = v.x - __half2float(__low2half(h));
    float ry = v.y - __half2float(__high2half(h));
    __half2 l = __floats2half2_rn(rx, ry);
    ((__half2*)g_xh_)[i] = h;
    ((__half2*)g_xl_)[i] = l;
}

// ---------------- transpose + convert weights: in [E][K][N] -> out [E][N][K] fp16 ----------------
template<bool IS_W1>
__global__ void tsplit_kernel(const float* __restrict__ in, int K, int N) {
    __half* oh = H16P(IS_W1 ? g_w1h_ : g_w2h_);
    __shared__ float t[32][33];
    int e = blockIdx.z;
    int n0 = blockIdx.x * 32, k0 = blockIdx.y * 32;
    const float* ine = in + (size_t)e * K * N;
    int tx = threadIdx.x, ty = threadIdx.y;
#pragma unroll
    for (int j = 0; j < 32; j += 8)
        t[ty + j][tx] = ine[(size_t)(k0 + ty + j) * N + n0 + tx];
    __syncthreads();
    size_t ob = (size_t)e * N * K;
#pragma unroll
    for (int j = 0; j < 32; j += 8) {
        float v = t[tx][ty + j];
        oh[ob + (size_t)(n0 + ty + j) * K + k0 + tx] = __float2half_rn(v);
    }
}

// ---------------- gate ----------------
__global__ void gate_kernel(const float* __restrict__ x, const float* __restrict__ wg) {
    int gwarp = (blockIdx.x * blockDim.x + threadIdx.x) >> 5;
    int lane  = threadIdx.x & 31;
    if (gwarp >= NTOK) return;
    const float* xr = x + (size_t)gwarp * DDIM;
    float acc[NEXP];
#pragma unroll
    for (int e = 0; e < NEXP; e++) acc[e] = 0.f;
#pragma unroll 4
    for (int i = 0; i < DDIM / 32; i++) {
        int d = lane + 32 * i;
        float xv = xr[d];
        const float* wr = wg + d * NEXP;
#pragma unroll
        for (int e = 0; e < NEXP; e++) acc[e] = fmaf(xv, wr[e], acc[e]);
    }
#pragma unroll
    for (int off = 16; off > 0; off >>= 1)
#pragma unroll
        for (int e = 0; e < NEXP; e++)
            acc[e] += __shfl_xor_sync(0xffffffffu, acc[e], off);

    if (lane == 0) {
        float m = acc[0];
#pragma unroll
        for (int e = 1; e < NEXP; e++) m = fmaxf(m, acc[e]);
        float p[NEXP]; float s = 0.f;
#pragma unroll
        for (int e = 0; e < NEXP; e++) { p[e] = expf(acc[e] - m); s += p[e]; }
        float inv = 1.f / s;
#pragma unroll
        for (int e = 0; e < NEXP; e++) { p[e] *= inv; g_scores[gwarp * NEXP + e] = p[e]; }
        int i1 = 0; float v1 = p[0];
#pragma unroll
        for (int e = 1; e < NEXP; e++) if (p[e] > v1) { v1 = p[e]; i1 = e; }
        int i2 = -1; float v2 = -1.f;
#pragma unroll
        for (int e = 0; e < NEXP; e++) if (e != i1 && p[e] > v2) { v2 = p[e]; i2 = e; }
        g_topv[gwarp * 2 + 0] = v1; g_topv[gwarp * 2 + 1] = v2;
        g_topi[gwarp * 2 + 0] = i1; g_topi[gwarp * 2 + 1] = i2;
        atomicAdd(&g_ce[i1], 1);
    }
}

// ---------------- routing ----------------
__global__ void route_kernel() {
    const int T = 512, PER = SLOTS / T;
    int t = threadIdx.x;
    int lane = t & 31, w = t >> 5;
    int base = t * PER;

    int cnt[NEXP];
#pragma unroll
    for (int e = 0; e < NEXP; e++) cnt[e] = 0;
    int myexp[PER];
#pragma unroll
    for (int i = 0; i < PER; i++) {
        int s = base + i;
        int slot = s >> 13;
        int n = s & (NTOK - 1);
        int e = g_topi[n * 2 + slot];
        myexp[i] = e;
        cnt[e]++;
    }
    int inc[NEXP];
#pragma unroll
    for (int e = 0; e < NEXP; e++) inc[e] = cnt[e];
#pragma unroll
    for (int o = 1; o < 32; o <<= 1) {
#pragma unroll
        for (int e = 0; e < NEXP; e++) {
            int v = __shfl_up_sync(0xffffffffu, inc[e], o);
            if (lane >= o) inc[e] += v;
        }
    }
    __shared__ int wtot[16][NEXP], wexcl[16][NEXP];
    if (lane == 31)
#pragma unroll
        for (int e = 0; e < NEXP; e++) wtot[w][e] = inc[e];
    __syncthreads();
    if (t == 0) {
        int run[NEXP];
#pragma unroll
        for (int e = 0; e < NEXP; e++) run[e] = 0;
        for (int ww = 0; ww < 16; ww++)
#pragma unroll
            for (int e = 0; e < NEXP; e++) { wexcl[ww][e] = run[e]; run[e] += wtot[ww][e]; }
    }
    __syncthreads();
    int off[NEXP];
#pragma unroll
    for (int e = 0; e < NEXP; e++) off[e] = wexcl[w][e] + inc[e] - cnt[e];
#pragma unroll
    for (int i = 0; i < PER; i++) {
        int e = myexp[i];
        int p = off[e]++;
        int s = base + i;
        g_pos[s] = p;
        if (p < CAP) {
            int n = s & (NTOK - 1);
            g_s2t[e * CAP + p] = n;
        }
    }
}

// ---------------- fp16x2 GEMM: 128x128 tile, 2-stage, static 36KB smem ----------------
#define BM 128
#define BN 128
#define BK 16
#define RPW 12   // uint32 words per row: 8 data (16 fp16) + 4 pad -> conflict-free

struct __align__(16) SmemT {
    uint32_t AH[2][BM][RPW];
    uint32_t AL[2][BM][RPW];
    uint32_t BH[2][BN][RPW];
};  // 36864 bytes

__device__ __forceinline__ void cp16(uint32_t dst, const void* src, int bytes) {
    asm volatile("cp.async.cg.shared.global [%0], [%1], 16, %2;\n"
                 :: "r"(dst), "l"(src), "r"(bytes));
}
__device__ __forceinline__ void cp_commit() { asm volatile("cp.async.commit_group;\n" ::); }
__device__ __forceinline__ void cp_wait1()  { asm volatile("cp.async.wait_group 1;\n" ::); }
__device__ __forceinline__ void cp_wait0()  { asm volatile("cp.async.wait_group 0;\n" ::); }

__device__ __forceinline__ void mma_f16(float* d, const uint32_t* a, const uint32_t* b) {
    asm volatile(
        "mma.sync.aligned.m16n8k16.row.col.f32.f16.f16.f32 "
        "{%0,%1,%2,%3}, {%4,%5,%6,%7}, {%8,%9}, {%0,%1,%2,%3};\n"
        : "+f"(d[0]), "+f"(d[1]), "+f"(d[2]), "+f"(d[3])
        : "r"(a[0]), "r"(a[1]), "r"(a[2]), "r"(a[3]), "r"(b[0]), "r"(b[1]));
}

// PHASE1: A = gather(xh/xl), B = fp16(w1) [E][H][D]; out g_hh/g_hl (relu+bias+split)
// PHASE2: A = g_hh/g_hl,     B = fp16(w2) [E][D][H]; out g_y (+bias)
template<int KD, int ND, bool PHASE1>
__global__ void __launch_bounds__(256) gemm_kernel(const float* __restrict__ bias)
{
    __shared__ SmemT S;
    const int e  = blockIdx.z;
    const int m0 = blockIdx.y * BM;
    const int n0 = blockIdx.x * BN;
    const float* be = bias + (size_t)e * ND;
    const int tid = threadIdx.x;

    // ---- loader: row = tid>>1, chunk = tid&1 (8 fp16 per chunk) ----
    const int lrow = tid >> 1;
    const int kce  = (tid & 1) * 8;
    const int kw   = (tid & 1) * 4;

    const __half *asrcH, *asrcL, *bsrcH;
    int abytes;
    if (PHASE1) {
        int tok = g_s2t[e * CAP + m0 + lrow];
        abytes = (tok >= 0) ? 16 : 0;
        size_t ao = (tok >= 0) ? ((size_t)tok * KD + kce) : 0;
        asrcH = CH16P(g_xh_) + ao;
        asrcL = CH16P(g_xl_) + ao;
    } else {
        abytes = 16;
        size_t ao = (size_t)(e * CAP + m0 + lrow) * KD + kce;
        asrcH = CH16P(g_hh_) + ao;
        asrcL = CH16P(g_hl_) + ao;
    }
    {
        size_t bo = (size_t)e * ND * KD + (size_t)(n0 + lrow) * KD + kce;
        bsrcH = CH16P(PHASE1 ? g_w1h_ : g_w2h_) + bo;
    }

    auto load_stage = [&](int buf, int kt) {
        size_t ko = (size_t)kt * BK;
        cp16((uint32_t)__cvta_generic_to_shared(&S.AH[buf][lrow][kw]), asrcH + ko, abytes);
        cp16((uint32_t)__cvta_generic_to_shared(&S.AL[buf][lrow][kw]), asrcL + ko, abytes);
        cp16((uint32_t)__cvta_generic_to_shared(&S.BH[buf][lrow][kw]), bsrcH + ko, 16);
        cp_commit();
    };

    // ---- warp tiling: 2x4 warps, each 64x32 ----
    const int warp = tid >> 5, lane = tid & 31;
    const int wm = warp >> 2, wn = warp & 3;
    const int mb = wm * 64, nb = wn * 32;
    const int lr = lane >> 2, lc = lane & 3;

    float acc[4][4][4];
#pragma unroll
    for (int mi = 0; mi < 4; mi++)
#pragma unroll
        for (int ni = 0; ni < 4; ni++)
#pragma unroll
            for (int r = 0; r < 4; r++) acc[mi][ni][r] = 0.f;

    const int KT = KD / BK;
    load_stage(0, 0);

    for (int kt = 0; kt < KT; kt++) {
        int buf = kt & 1;
        if (kt + 1 < KT) { load_stage(buf ^ 1, kt + 1); cp_wait1(); }
        else             { cp_wait0(); }
        __syncthreads();

        uint32_t afh[4][4], afl[4][4];
#pragma unroll
        for (int mi = 0; mi < 4; mi++) {
            int row = mb + mi * 16 + lr;
            afh[mi][0] = S.AH[buf][row][lc];
            afh[mi][1] = S.AH[buf][row + 8][lc];
            afh[mi][2] = S.AH[buf][row][lc + 4];
            afh[mi][3] = S.AH[buf][row + 8][lc + 4];
            afl[mi][0] = S.AL[buf][row][lc];
            afl[mi][1] = S.AL[buf][row + 8][lc];
            afl[mi][2] = S.AL[buf][row][lc + 4];
            afl[mi][3] = S.AL[buf][row + 8][lc + 4];
        }
        uint32_t bh[4][2];
#pragma unroll
        for (int ni = 0; ni < 4; ni++) {
            int col = nb + ni * 8 + lr;
            bh[ni][0] = S.BH[buf][col][lc];
            bh[ni][1] = S.BH[buf][col][lc + 4];
        }
        // two passes: same-acc MMAs spaced 16 apart
#pragma unroll
        for (int mi = 0; mi < 4; mi++)
#pragma unroll
            for (int ni = 0; ni < 4; ni++)
                mma_f16(acc[mi][ni], afl[mi], bh[ni]);   // lo*b
#pragma unroll
        for (int mi = 0; mi < 4; mi++)
#pragma unroll
            for (int ni = 0; ni < 4; ni++)
                mma_f16(acc[mi][ni], afh[mi], bh[ni]);   // hi*b
        __syncthreads();
    }

    // ---- epilogue ----
#pragma unroll
    for (int mi = 0; mi < 4; mi++) {
        int r = m0 + mb + mi * 16 + lr;
#pragma unroll
        for (int ni = 0; ni < 4; ni++) {
            int cb = n0 + nb + ni * 8 + 2 * lc;
            float b0 = be[cb], b1 = be[cb + 1];
            float v0 = acc[mi][ni][0] + b0, v1 = acc[mi][ni][1] + b1;
            float v2 = acc[mi][ni][2] + b0, v3 = acc[mi][ni][3] + b1;
            if (PHASE1) {
                v0 = fmaxf(v0, 0.f); v1 = fmaxf(v1, 0.f);
                v2 = fmaxf(v2, 0.f); v3 = fmaxf(v3, 0.f);
                size_t s0 = (size_t)(e * CAP + r) * HDIM + cb;
                size_t s1 = (size_t)(e * CAP + r + 8) * HDIM + cb;
                __half2 h0 = __floats2half2_rn(v0, v1);
                __half2 h1 = __floats2half2_rn(v2, v3);
                __half2 l0 = __floats2half2_rn(v0 - __half2float(__low2half(h0)),
                                               v1 - __half2float(__high2half(h0)));
                __half2 l1 = __floats2half2_rn(v2 - __half2float(__low2half(h1)),
                                               v3 - __half2float(__high2half(h1)));
                *(__half2*)(H16P(g_hh_) + s0) = h0;
                *(__half2*)(H16P(g_hh_) + s1) = h1;
                *(__half2*)(H16P(g_hl_) + s0) = l0;
                *(__half2*)(H16P(g_hl_) + s1) = l1;
            } else {
                float* Ce = g_y + (size_t)e * CAP * DDIM;
                *(float2*)&Ce[(size_t)r * DDIM + cb]       = make_float2(v0, v1);
                *(float2*)&Ce[(size_t)(r + 8) * DDIM + cb] = make_float2(v2, v3);
            }
        }
    }
}

// ---------------- combine ----------------
__global__ void combine_kernel(float* __restrict__ out) {
    int n = blockIdx.x, tid = threadIdx.x;
    float4 acc = make_float4(0.f, 0.f, 0.f, 0.f);
#pragma unroll
    for (int slot = 0; slot < TOPK; slot++) {
        int p = g_pos[slot * NTOK + n];
        if (p < CAP) {
            float v = g_topv[n * 2 + slot];
            int e = g_topi[n * 2 + slot];
            const float4* row = (const float4*)(g_y + (size_t)(e * CAP + p) * DDIM);
            float4 f = row[tid];
            acc.x += v * f.x; acc.y += v * f.y; acc.z += v * f.z; acc.w += v * f.w;
        }
    }
    ((float4*)(out + (size_t)n * DDIM))[tid] = acc;
}

// ---------------- aux loss ----------------
__global__ void aux_kernel(float* __restrict__ out, int out_size) {
    __shared__ float s[256];
    int tid = threadIdx.x;
    float p[NEXP];
#pragma unroll
    for (int e = 0; e < NEXP; e++) p[e] = 0.f;
    for (int i = tid; i < NTOK; i += 256)
#pragma unroll
        for (int e = 0; e < NEXP; e++) p[e] += g_scores[i * NEXP + e];

    float total = 0.f;
#pragma unroll
    for (int e = 0; e < NEXP; e++) {
        s[tid] = p[e];
        __syncthreads();
        for (int st = 128; st > 0; st >>= 1) {
            if (tid < st) s[tid] += s[tid + st];
            __syncthreads();
        }
        if (tid == 0) {
            float me = s[0] / (float)NTOK;
            float ce = (float)g_ce[e] / (float)NTOK;
            total += me * ce;
        }
        __syncthreads();
    }
    if (tid == 0) {
        float laux = (float)NEXP * total;
        for (long i = (long)NTOK * DDIM; i < (long)out_size; i++) out[i] = laux;
    }
}

// ---------------- launch ----------------
extern "C" void kernel_launch(void* const* d_in, const int* in_sizes, int n_in,
                              void* d_out, int out_size) {
    const float* x    = (const float*)d_in[0];
    const float* wg   = (const float*)d_in[1];
    const float* fc1w = (const float*)d_in[2];
    const float* fc1b = (const float*)d_in[3];
    const float* fc2w = (const float*)d_in[4];
    const float* fc2b = (const float*)d_in[5];
    float* out = (float*)d_out;
    (void)in_sizes; (void)n_in;

    init_kernel<<<(NEXP * CAP + 255) / 256, 256>>>();
    split_x_kernel<<<(NTOK * DDIM / 2 + 255) / 256, 256>>>(x);
    tsplit_kernel<true ><<<dim3(HDIM / 32, DDIM / 32, NEXP), dim3(32, 8)>>>(fc1w, DDIM, HDIM);
    tsplit_kernel<false><<<dim3(DDIM / 32, HDIM / 32, NEXP), dim3(32, 8)>>>(fc2w, HDIM, DDIM);
    gate_kernel<<<NTOK / 8, 256>>>(x, wg);
    route_kernel<<<1, 512>>>();
    gemm_kernel<DDIM, HDIM, true ><<<dim3(HDIM / BN, CAP / BM, NEXP), 256>>>(fc1b);
    gemm_kernel<HDIM, DDIM, false><<<dim3(DDIM / BN, CAP / BM, NEXP), 256>>>(fc2b);
    combine_kernel<<<NTOK, 256>>>(out);
    aux_kernel<<<1, 256>>>(out, out_size);
}

// round 10
// speedup vs baseline: 1.9960x; 1.3186x over previous
#include <cuda_runtime.h>
#include <cuda_bf16.h>
#include <cuda_fp16.h>
#include <cstdint>

// Problem constants
#define NTOK 8192
#define DDIM 1024
#define HDIM 4096
#define NEXP 8
#define TOPK 2
#define CAP  2048          // (TOPK*NTOK)/NEXP
#define SLOTS (TOPK*NTOK)  // 16384

// ---------------- scratch (__device__ globals: allocation-free) ----------------
__device__ float g_scores[NTOK * NEXP];
__device__ float g_topv[NTOK * TOPK];
__device__ int   g_topi[NTOK * TOPK];
__device__ int   g_pos[SLOTS];
__device__ int   g_s2t[NEXP * CAP];
__device__ int   g_ce[NEXP];
// fp16 operands; uint4 backing guarantees 16B alignment
__device__ uint4 g_xh_[(size_t)NTOK * DDIM / 8];          // x hi
__device__ uint4 g_xl_[(size_t)NTOK * DDIM / 8];          // x lo (exact residual)
__device__ uint4 g_w1h_[(size_t)NEXP * HDIM * DDIM / 8];  // [E][n=H][k=D] fp16(w1)
__device__ uint4 g_w2h_[(size_t)NEXP * DDIM * HDIM / 8];  // [E][n=D][k=H] fp16(w2)
__device__ uint4 g_hh_[(size_t)NEXP * CAP * HDIM / 8];    // h hi
__device__ uint4 g_hl_[(size_t)NEXP * CAP * HDIM / 8];    // h lo
__device__ float g_y[(size_t)NEXP * CAP * DDIM];

#define H16P(a) (( __half*)(a))
#define CH16P(a) ((const __half*)(a))

// ---------------- init ----------------
__global__ void init_kernel() {
    int i = blockIdx.x * blockDim.x + threadIdx.x;
    if (i < NEXP * CAP) g_s2t[i] = -1;
    if (i < NEXP)       g_ce[i]  = 0;
}

// ---------------- split x -> fp16 hi/lo ----------------
__global__ void split_x_kernel(const float* __restrict__ x) {
    int i = blockIdx.x * blockDim.x + threadIdx.x;
    const int NP = NTOK * DDIM / 2;
    if (i >= NP) return;
    float2 v = ((const float2*)x)[i];
    __half2 h = __floats2half2_rn(v.x, v.y);
    float rx = v.x - __half2float(__low2half(h));
    float ry = v.y - __half2float(__high2half(h));
    __half2 l = __floats2half2_rn(rx, ry);
    ((__half2*)g_xh_)[i] = h;
    ((__half2*)g_xl_)[i] = l;
}

// ---------------- transpose + convert weights: in [E][K][N] -> out [E][N][K] fp16 ----------------
template<bool IS_W1>
__global__ void tsplit_kernel(const float* __restrict__ in, int K, int N) {
    __half* oh = H16P(IS_W1 ? g_w1h_ : g_w2h_);
    __shared__ float t[32][33];
    int e = blockIdx.z;
    int n0 = blockIdx.x * 32, k0 = blockIdx.y * 32;
    const float* ine = in + (size_t)e * K * N;
    int tx = threadIdx.x, ty = threadIdx.y;
#pragma unroll
    for (int j = 0; j < 32; j += 8)
        t[ty + j][tx] = ine[(size_t)(k0 + ty + j) * N + n0 + tx];
    __syncthreads();
    size_t ob = (size_t)e * N * K;
#pragma unroll
    for (int j = 0; j < 32; j += 8) {
        float v = t[tx][ty + j];
        oh[ob + (size_t)(n0 + ty + j) * K + k0 + tx] = __float2half_rn(v);
    }
}

// ---------------- gate ----------------
__global__ void gate_kernel(const float* __restrict__ x, const float* __restrict__ wg) {
    int gwarp = (blockIdx.x * blockDim.x + threadIdx.x) >> 5;
    int lane  = threadIdx.x & 31;
    if (gwarp >= NTOK) return;
    const float* xr = x + (size_t)gwarp * DDIM;
    float acc[NEXP];
#pragma unroll
    for (int e = 0; e < NEXP; e++) acc[e] = 0.f;
#pragma unroll 4
    for (int i = 0; i < DDIM / 32; i++) {
        int d = lane + 32 * i;
        float xv = xr[d];
        const float* wr = wg + d * NEXP;
#pragma unroll
        for (int e = 0; e < NEXP; e++) acc[e] = fmaf(xv, wr[e], acc[e]);
    }
#pragma unroll
    for (int off = 16; off > 0; off >>= 1)
#pragma unroll
        for (int e = 0; e < NEXP; e++)
            acc[e] += __shfl_xor_sync(0xffffffffu, acc[e], off);

    if (lane == 0) {
        float m = acc[0];
#pragma unroll
        for (int e = 1; e < NEXP; e++) m = fmaxf(m, acc[e]);
        float p[NEXP]; float s = 0.f;
#pragma unroll
        for (int e = 0; e < NEXP; e++) { p[e] = expf(acc[e] - m); s += p[e]; }
        float inv = 1.f / s;
#pragma unroll
        for (int e = 0; e < NEXP; e++) { p[e] *= inv; g_scores[gwarp * NEXP + e] = p[e]; }
        int i1 = 0; float v1 = p[0];
#pragma unroll
        for (int e = 1; e < NEXP; e++) if (p[e] > v1) { v1 = p[e]; i1 = e; }
        int i2 = -1; float v2 = -1.f;
#pragma unroll
        for (int e = 0; e < NEXP; e++) if (e != i1 && p[e] > v2) { v2 = p[e]; i2 = e; }
        g_topv[gwarp * 2 + 0] = v1; g_topv[gwarp * 2 + 1] = v2;
        g_topi[gwarp * 2 + 0] = i1; g_topi[gwarp * 2 + 1] = i2;
        atomicAdd(&g_ce[i1], 1);
    }
}

// ---------------- routing ----------------
__global__ void route_kernel() {
    const int T = 512, PER = SLOTS / T;
    int t = threadIdx.x;
    int lane = t & 31, w = t >> 5;
    int base = t * PER;

    int cnt[NEXP];
#pragma unroll
    for (int e = 0; e < NEXP; e++) cnt[e] = 0;
    int myexp[PER];
#pragma unroll
    for (int i = 0; i < PER; i++) {
        int s = base + i;
        int slot = s >> 13;
        int n = s & (NTOK - 1);
        int e = g_topi[n * 2 + slot];
        myexp[i] = e;
        cnt[e]++;
    }
    int inc[NEXP];
#pragma unroll
    for (int e = 0; e < NEXP; e++) inc[e] = cnt[e];
#pragma unroll
    for (int o = 1; o < 32; o <<= 1) {
#pragma unroll
        for (int e = 0; e < NEXP; e++) {
            int v = __shfl_up_sync(0xffffffffu, inc[e], o);
            if (lane >= o) inc[e] += v;
        }
    }
    __shared__ int wtot[16][NEXP], wexcl[16][NEXP];
    if (lane == 31)
#pragma unroll
        for (int e = 0; e < NEXP; e++) wtot[w][e] = inc[e];
    __syncthreads();
    if (t == 0) {
        int run[NEXP];
#pragma unroll
        for (int e = 0; e < NEXP; e++) run[e] = 0;
        for (int ww = 0; ww < 16; ww++)
#pragma unroll
            for (int e = 0; e < NEXP; e++) { wexcl[ww][e] = run[e]; run[e] += wtot[ww][e]; }
    }
    __syncthreads();
    int off[NEXP];
#pragma unroll
    for (int e = 0; e < NEXP; e++) off[e] = wexcl[w][e] + inc[e] - cnt[e];
#pragma unroll
    for (int i = 0; i < PER; i++) {
        int e = myexp[i];
        int p = off[e]++;
        int s = base + i;
        g_pos[s] = p;
        if (p < CAP) {
            int n = s & (NTOK - 1);
            g_s2t[e * CAP + p] = n;
        }
    }
}

// ---------------- fp16x2 GEMM: 128x128 tile, BK=32, ldmatrix, dynamic smem ----------------
#define BM 128
#define BN 128
#define BK 32
#define RPW 20   // uint32 words per row: 16 data (32 fp16) + 4 pad (pitch 80B, conflict-free LDSM)
#define TSTRIDE (128 * RPW * 4)          // 10240 B per tensor-stage
#define AH_OFF(s) ((uint32_t)((s) * TSTRIDE))
#define AL_OFF(s) ((uint32_t)(2 * TSTRIDE + (s) * TSTRIDE))
#define BH_OFF(s) ((uint32_t)(4 * TSTRIDE + (s) * TSTRIDE))
#define SMEM_DYN (6 * TSTRIDE)           // 61440 B

__device__ __forceinline__ void cp16(uint32_t dst, const void* src, int bytes) {
    asm volatile("cp.async.cg.shared.global [%0], [%1], 16, %2;\n"
                 :: "r"(dst), "l"(src), "r"(bytes));
}
__device__ __forceinline__ void cp_commit() { asm volatile("cp.async.commit_group;\n" ::); }
__device__ __forceinline__ void cp_wait1()  { asm volatile("cp.async.wait_group 1;\n" ::); }
__device__ __forceinline__ void cp_wait0()  { asm volatile("cp.async.wait_group 0;\n" ::); }

__device__ __forceinline__ void mma_f16(float* d, const uint32_t* a, const uint32_t* b) {
    asm volatile(
        "mma.sync.aligned.m16n8k16.row.col.f32.f16.f16.f32 "
        "{%0,%1,%2,%3}, {%4,%5,%6,%7}, {%8,%9}, {%0,%1,%2,%3};\n"
        : "+f"(d[0]), "+f"(d[1]), "+f"(d[2]), "+f"(d[3])
        : "r"(a[0]), "r"(a[1]), "r"(a[2]), "r"(a[3]), "r"(b[0]), "r"(b[1]));
}
__device__ __forceinline__ void ldsm4(uint32_t* r, uint32_t addr) {
    asm volatile("ldmatrix.sync.aligned.m8n8.x4.shared.b16 {%0,%1,%2,%3}, [%4];"
                 : "=r"(r[0]), "=r"(r[1]), "=r"(r[2]), "=r"(r[3]) : "r"(addr));
}

// PHASE1: A = gather(xh/xl), B = fp16(w1) [E][H][D]; out g_hh/g_hl (relu+bias+split)
// PHASE2: A = g_hh/g_hl,     B = fp16(w2) [E][D][H]; out g_y (+bias)
template<int KD, int ND, bool PHASE1>
__global__ void __launch_bounds__(256, 2) gemm_kernel(const float* __restrict__ bias)
{
    extern __shared__ char smraw[];
    const uint32_t sbase = (uint32_t)__cvta_generic_to_shared(smraw);
    const int e  = blockIdx.z;
    const int m0 = blockIdx.y * BM;
    const int n0 = blockIdx.x * BN;
    const float* be = bias + (size_t)e * ND;
    const int tid = threadIdx.x;

    // ---- loader: 512 chunks of 16B per tensor per stage; 2 per thread ----
    // chunk c: row = c>>2 (0..127), g = c&3 -> words g*4..g*4+3, src elems g*8..
    const __half *asrcH[2], *asrcL[2], *bsrcH[2];
    int aok[2]; uint32_t sdst[2];
#pragma unroll
    for (int i = 0; i < 2; i++) {
        int c = tid + i * 256;
        int row = c >> 2, g = c & 3;
        sdst[i] = (uint32_t)(row * 80 + g * 16);
        if (PHASE1) {
            int tok = g_s2t[e * CAP + m0 + row];
            aok[i] = (tok >= 0) ? 16 : 0;
            size_t ao = (tok >= 0) ? ((size_t)tok * KD + g * 8) : 0;
            asrcH[i] = CH16P(g_xh_) + ao;
            asrcL[i] = CH16P(g_xl_) + ao;
        } else {
            aok[i] = 16;
            size_t ao = (size_t)(e * CAP + m0 + row) * KD + g * 8;
            asrcH[i] = CH16P(g_hh_) + ao;
            asrcL[i] = CH16P(g_hl_) + ao;
        }
        size_t bo = (size_t)e * ND * KD + (size_t)(n0 + row) * KD + g * 8;
        bsrcH[i] = CH16P(PHASE1 ? g_w1h_ : g_w2h_) + bo;
    }

    auto load_stage = [&](int buf, int kt) {
        size_t ko = (size_t)kt * BK;
#pragma unroll
        for (int i = 0; i < 2; i++) {
            cp16(sbase + AH_OFF(buf) + sdst[i], asrcH[i] + ko, aok[i]);
            cp16(sbase + AL_OFF(buf) + sdst[i], asrcL[i] + ko, aok[i]);
            cp16(sbase + BH_OFF(buf) + sdst[i], bsrcH[i] + ko, 16);
        }
        cp_commit();
    };

    // ---- warp tiling: 2x4 warps, each 64x32 ----
    const int warp = tid >> 5, lane = tid & 31;
    const int wm = warp >> 2, wn = warp & 3;
    const int mb = wm * 64, nb = wn * 32;
    const int lr = lane >> 2, lc = lane & 3;

    // ldmatrix per-lane address components (bytes)
    // A x4: lane 0-15 -> rows r..r+15 (k lo-half word), lane 16-31 same rows k-hi word (+16B)
    const uint32_t a_lane = (uint32_t)((mb + (lane & 15)) * 80 + ((lane >> 4) & 1) * 16);
    // B x4 (pair p): lanes 0-7: col(+0) k0; 8-15: col(+0) k8; 16-23: col(+8) k0; 24-31: col(+8) k8
    const uint32_t b_lane0 = (uint32_t)((nb + ((lane >> 4) & 1) * 8 + (lane & 7)) * 80
                                        + ((lane >> 3) & 1) * 16);

    float acc[4][4][4];
#pragma unroll
    for (int mi = 0; mi < 4; mi++)
#pragma unroll
        for (int ni = 0; ni < 4; ni++)
#pragma unroll
            for (int r = 0; r < 4; r++) acc[mi][ni][r] = 0.f;

    const int KT = KD / BK;
    load_stage(0, 0);

    for (int kt = 0; kt < KT; kt++) {
        int buf = kt & 1;
        if (kt + 1 < KT) { load_stage(buf ^ 1, kt + 1); cp_wait1(); }
        else             { cp_wait0(); }
        __syncthreads();

        const uint32_t ah_s = sbase + AH_OFF(buf);
        const uint32_t al_s = sbase + AL_OFF(buf);
        const uint32_t bh_s = sbase + BH_OFF(buf);

#pragma unroll
        for (int ks = 0; ks < 2; ks++) {
            const uint32_t ksb = (uint32_t)(ks * 32);
            // B fragments: 2 x4 = bh[0..3][0..1]
            uint32_t bh[4][2];
            ldsm4(&bh[0][0], bh_s + ksb + b_lane0);            // p=0 -> bh[0],bh[1]
            ldsm4(&bh[2][0], bh_s + ksb + b_lane0 + 16 * 80);  // p=1 -> bh[2],bh[3]
            uint32_t af[4][4];
            // lo pass
#pragma unroll
            for (int mi = 0; mi < 4; mi++)
                ldsm4(af[mi], al_s + ksb + a_lane + (uint32_t)(mi * 16 * 80));
#pragma unroll
            for (int mi = 0; mi < 4; mi++)
#pragma unroll
                for (int ni = 0; ni < 4; ni++)
                    mma_f16(acc[mi][ni], af[mi], bh[ni]);
            // hi pass (reuse af regs)
#pragma unroll
            for (int mi = 0; mi < 4; mi++)
                ldsm4(af[mi], ah_s + ksb + a_lane + (uint32_t)(mi * 16 * 80));
#pragma unroll
            for (int mi = 0; mi < 4; mi++)
#pragma unroll
                for (int ni = 0; ni < 4; ni++)
                    mma_f16(acc[mi][ni], af[mi], bh[ni]);
        }
        __syncthreads();
    }

    // ---- epilogue ----
#pragma unroll
    for (int mi = 0; mi < 4; mi++) {
        int r = m0 + mb + mi * 16 + lr;
#pragma unroll
        for (int ni = 0; ni < 4; ni++) {
            int cb = n0 + nb + ni * 8 + 2 * lc;
            float b0 = be[cb], b1 = be[cb + 1];
            float v0 = acc[mi][ni][0] + b0, v1 = acc[mi][ni][1] + b1;
            float v2 = acc[mi][ni][2] + b0, v3 = acc[mi][ni][3] + b1;
            if (PHASE1) {
                v0 = fmaxf(v0, 0.f); v1 = fmaxf(v1, 0.f);
                v2 = fmaxf(v2, 0.f); v3 = fmaxf(v3, 0.f);
                size_t s0 = (size_t)(e * CAP + r) * HDIM + cb;
                size_t s1 = (size_t)(e * CAP + r + 8) * HDIM + cb;
                __half2 h0 = __floats2half2_rn(v0, v1);
                __half2 h1 = __floats2half2_rn(v2, v3);
                __half2 l0 = __floats2half2_rn(v0 - __half2float(__low2half(h0)),
                                               v1 - __half2float(__high2half(h0)));
                __half2 l1 = __floats2half2_rn(v2 - __half2float(__low2half(h1)),
                                               v3 - __half2float(__high2half(h1)));
                *(__half2*)(H16P(g_hh_) + s0) = h0;
                *(__half2*)(H16P(g_hh_) + s1) = h1;
                *(__half2*)(H16P(g_hl_) + s0) = l0;
                *(__half2*)(H16P(g_hl_) + s1) = l1;
            } else {
                float* Ce = g_y + (size_t)e * CAP * DDIM;
                *(float2*)&Ce[(size_t)r * DDIM + cb]       = make_float2(v0, v1);
                *(float2*)&Ce[(size_t)(r + 8) * DDIM + cb] = make_float2(v2, v3);
            }
        }
    }
}

// ---------------- combine ----------------
__global__ void combine_kernel(float* __restrict__ out) {
    int n = blockIdx.x, tid = threadIdx.x;
    float4 acc = make_float4(0.f, 0.f, 0.f, 0.f);
#pragma unroll
    for (int slot = 0; slot < TOPK; slot++) {
        int p = g_pos[slot * NTOK + n];
        if (p < CAP) {
            float v = g_topv[n * 2 + slot];
            int e = g_topi[n * 2 + slot];
            const float4* row = (const float4*)(g_y + (size_t)(e * CAP + p) * DDIM);
            float4 f = row[tid];
            acc.x += v * f.x; acc.y += v * f.y; acc.z += v * f.z; acc.w += v * f.w;
        }
    }
    ((float4*)(out + (size_t)n * DDIM))[tid] = acc;
}

// ---------------- aux loss ----------------
__global__ void aux_kernel(float* __restrict__ out, int out_size) {
    __shared__ float s[256];
    int tid = threadIdx.x;
    float p[NEXP];
#pragma unroll
    for (int e = 0; e < NEXP; e++) p[e] = 0.f;
    for (int i = tid; i < NTOK; i += 256)
#pragma unroll
        for (int e = 0; e < NEXP; e++) p[e] += g_scores[i * NEXP + e];

    float total = 0.f;
#pragma unroll
    for (int e = 0; e < NEXP; e++) {
        s[tid] = p[e];
        __syncthreads();
        for (int st = 128; st > 0; st >>= 1) {
            if (tid < st) s[tid] += s[tid + st];
            __syncthreads();
        }
        if (tid == 0) {
            float me = s[0] / (float)NTOK;
            float ce = (float)g_ce[e] / (float)NTOK;
            total += me * ce;
        }
        __syncthreads();
    }
    if (tid == 0) {
        float laux = (float)NEXP * total;
        for (long i = (long)NTOK * DDIM; i < (long)out_size; i++) out[i] = laux;
    }
}

// ---------------- launch ----------------
extern "C" void kernel_launch(void* const* d_in, const int* in_sizes, int n_in,
                              void* d_out, int out_size) {
    const float* x    = (const float*)d_in[0];
    const float* wg   = (const float*)d_in[1];
    const float* fc1w = (const float*)d_in[2];
    const float* fc1b = (const float*)d_in[3];
    const float* fc2w = (const float*)d_in[4];
    const float* fc2b = (const float*)d_in[5];
    float* out = (float*)d_out;
    (void)in_sizes; (void)n_in;

    cudaFuncSetAttribute(gemm_kernel<DDIM, HDIM, true >,
                         cudaFuncAttributeMaxDynamicSharedMemorySize, SMEM_DYN);
    cudaFuncSetAttribute(gemm_kernel<HDIM, DDIM, false>,
                         cudaFuncAttributeMaxDynamicSharedMemorySize, SMEM_DYN);

    init_kernel<<<(NEXP * CAP + 255) / 256, 256>>>();
    split_x_kernel<<<(NTOK * DDIM / 2 + 255) / 256, 256>>>(x);
    tsplit_kernel<true ><<<dim3(HDIM / 32, DDIM / 32, NEXP), dim3(32, 8)>>>(fc1w, DDIM, HDIM);
    tsplit_kernel<false><<<dim3(DDIM / 32, HDIM / 32, NEXP), dim3(32, 8)>>>(fc2w, HDIM, DDIM);
    gate_kernel<<<NTOK / 8, 256>>>(x, wg);
    route_kernel<<<1, 512>>>();
    gemm_kernel<DDIM, HDIM, true ><<<dim3(HDIM / BN, CAP / BM, NEXP), 256, SMEM_DYN>>>(fc1b);
    gemm_kernel<HDIM, DDIM, false><<<dim3(DDIM / BN, CAP / BM, NEXP), 256, SMEM_DYN>>>(fc2b);
    combine_kernel<<<NTOK, 256>>>(out);
    aux_kernel<<<1, 256>>>(out, out_size);
}